// round 1
// baseline (speedup 1.0000x reference)
#include <cuda_runtime.h>

#define D 4096
#define NV4 (D / 4)        // 1024 float4 per row
#define THREADS 512
#define EPS 1e-6f

__global__ __launch_bounds__(THREADS) void mrmsnorm_kernel(
    const float4* __restrict__ x,
    const float4* __restrict__ scale,
    float4* __restrict__ out)
{
    const size_t row = blockIdx.x;
    const float4* __restrict__ xr = x + row * NV4;
    float4* __restrict__ orow = out + row * NV4;

    const int t = threadIdx.x;

    __shared__ float ssum[5];
    if (t < 5) ssum[t] = 0.0f;
    __syncthreads();

    // Each thread loads two float4s: indices t (first half) and t+512 (second half).
    float4 a = xr[t];
    float4 b = xr[t + THREADS];

    float sa = a.x * a.x + a.y * a.y + a.z * a.z + a.w * a.w;
    float sb = b.x * b.x + b.y * b.y + b.z * b.z + b.w * b.w;

    // Warp-level tree reduce both partial sums.
    #pragma unroll
    for (int o = 16; o > 0; o >>= 1) {
        sa += __shfl_down_sync(0xffffffffu, sa, o);
        sb += __shfl_down_sync(0xffffffffu, sb, o);
    }

    const int lane = t & 31;
    if (lane == 0) {
        // float4-index segment boundaries: 64, 128, 256, 512 (all multiples of 32),
        // so the whole warp's first-half elements share one segment.
        int v = t;  // warp-base float4 index (lane 0)
        int seg = (v < 64) ? 0 : (v < 128) ? 1 : (v < 256) ? 2 : 3;
        atomicAdd(&ssum[seg], sa);
        atomicAdd(&ssum[4], sb);   // second half (indices 512..1023) is all segment 4
    }
    __syncthreads();

    // Prefix sums of segment sums -> cumulative sum-of-squares at each checkpoint.
    float c0 = ssum[0];
    float c1 = c0 + ssum[1];
    float c2 = c1 + ssum[2];
    float c3 = c2 + ssum[3];
    float c4 = c3 + ssum[4];

    float r0 = rsqrtf(c0 * (1.0f / 256.0f) + EPS);
    float r1 = rsqrtf(c1 * (1.0f / 512.0f) + EPS);
    float r2 = rsqrtf(c2 * (1.0f / 1024.0f) + EPS);
    float r3 = rsqrtf(c3 * (1.0f / 2048.0f) + EPS);
    float r4 = rsqrtf(c4 * (1.0f / 4096.0f) + EPS);

    float ra = (t < 64) ? r0 : (t < 128) ? r1 : (t < 256) ? r2 : r3;
    float rb = r4;

    float4 s0 = scale[t];
    float4 s1 = scale[t + THREADS];

    float4 oa, ob;
    oa.x = a.x * ra * s0.x;
    oa.y = a.y * ra * s0.y;
    oa.z = a.z * ra * s0.z;
    oa.w = a.w * ra * s0.w;
    ob.x = b.x * rb * s1.x;
    ob.y = b.y * rb * s1.y;
    ob.z = b.z * rb * s1.z;
    ob.w = b.w * rb * s1.w;

    orow[t] = oa;
    orow[t + THREADS] = ob;
}

extern "C" void kernel_launch(void* const* d_in, const int* in_sizes, int n_in,
                              void* d_out, int out_size)
{
    const float4* x = (const float4*)d_in[0];
    const float4* scale = (const float4*)d_in[1];
    float4* out = (float4*)d_out;

    const int rows = out_size / D;   // 4 * 4096 = 16384
    mrmsnorm_kernel<<<rows, THREADS>>>(x, scale, out);
}

// round 2
// speedup vs baseline: 1.0805x; 1.0805x over previous
#include <cuda_runtime.h>

#define D 4096
#define NV4 (D / 4)        // 1024 float4 per row
#define THREADS 256
#define EPS 1e-6f

__global__ __launch_bounds__(THREADS) void mrmsnorm_kernel(
    const float4* __restrict__ x,
    const float4* __restrict__ scale,
    float4* __restrict__ out)
{
    const size_t row = blockIdx.x;
    const float4* __restrict__ xr = x + row * NV4;
    float4* __restrict__ orow = out + row * NV4;

    const int t = threadIdx.x;
    const int warp = t >> 5;
    const int lane = t & 31;

    // Four front-batched streaming loads per thread (evict-first: no reuse of x).
    float4 a = __ldcs(&xr[t]);
    float4 b = __ldcs(&xr[t + THREADS]);
    float4 c = __ldcs(&xr[t + 2 * THREADS]);
    float4 d = __ldcs(&xr[t + 3 * THREADS]);

    float sa = a.x * a.x + a.y * a.y + a.z * a.z + a.w * a.w;
    float sb = b.x * b.x + b.y * b.y + b.z * b.z + b.w * b.w;
    float sc = c.x * c.x + c.y * c.y + c.z * c.z + c.w * c.w;
    float sd = d.x * d.x + d.y * d.y + d.z * d.z + d.w * d.w;
    float scd = sc + sd;

    // Warp tree-reduce the three per-thread partials.
    #pragma unroll
    for (int o = 16; o > 0; o >>= 1) {
        sa  += __shfl_down_sync(0xffffffffu, sa, o);
        sb  += __shfl_down_sync(0xffffffffu, sb, o);
        scd += __shfl_down_sync(0xffffffffu, scd, o);
    }

    // Per-warp partials -> smem, one barrier, no atomics.
    // Float4-index ranges per slice (8 warps of 32):
    //   a: idx t        in [0,256)   -> seg0 (warps 0,1), seg1 (2,3), seg2 (4..7)
    //   b: idx t+256    in [256,512) -> seg3 (all warps)
    //   c,d: idx >= 512              -> seg4 (all warps)
    __shared__ float ws[8][3];
    if (lane == 0) {
        ws[warp][0] = sa;
        ws[warp][1] = sb;
        ws[warp][2] = scd;
    }
    __syncthreads();

    float seg0 = ws[0][0] + ws[1][0];
    float seg1 = ws[2][0] + ws[3][0];
    float seg2 = ws[4][0] + ws[5][0] + ws[6][0] + ws[7][0];
    float seg3 = ws[0][1] + ws[1][1] + ws[2][1] + ws[3][1]
               + ws[4][1] + ws[5][1] + ws[6][1] + ws[7][1];
    float seg4 = ws[0][2] + ws[1][2] + ws[2][2] + ws[3][2]
               + ws[4][2] + ws[5][2] + ws[6][2] + ws[7][2];

    float c0 = seg0;
    float c1 = c0 + seg1;
    float c2 = c1 + seg2;
    float c3 = c2 + seg3;
    float c4 = c3 + seg4;

    float r0 = rsqrtf(c0 * (1.0f / 256.0f)  + EPS);
    float r1 = rsqrtf(c1 * (1.0f / 512.0f)  + EPS);
    float r2 = rsqrtf(c2 * (1.0f / 1024.0f) + EPS);
    float r3 = rsqrtf(c3 * (1.0f / 2048.0f) + EPS);
    float r4 = rsqrtf(c4 * (1.0f / 4096.0f) + EPS);

    // Slice-a rrms is warp-uniform (boundaries 64/128 are multiples of 32).
    float ra = (t < 64) ? r0 : (t < 128) ? r1 : r2;
    float rb = r3;   // [256,512)
    float rc = r4;   // [512,1024)

    float4 s0 = scale[t];
    float4 s1 = scale[t + THREADS];
    float4 s2 = scale[t + 2 * THREADS];
    float4 s3 = scale[t + 3 * THREADS];

    float4 o0, o1, o2, o3;
    o0.x = a.x * ra * s0.x;  o0.y = a.y * ra * s0.y;
    o0.z = a.z * ra * s0.z;  o0.w = a.w * ra * s0.w;
    o1.x = b.x * rb * s1.x;  o1.y = b.y * rb * s1.y;
    o1.z = b.z * rb * s1.z;  o1.w = b.w * rb * s1.w;
    o2.x = c.x * rc * s2.x;  o2.y = c.y * rc * s2.y;
    o2.z = c.z * rc * s2.z;  o2.w = c.w * rc * s2.w;
    o3.x = d.x * rc * s3.x;  o3.y = d.y * rc * s3.y;
    o3.z = d.z * rc * s3.z;  o3.w = d.w * rc * s3.w;

    // Streaming stores: out is write-once, keep it out of L2's working set.
    __stcs(&orow[t],               o0);
    __stcs(&orow[t + THREADS],     o1);
    __stcs(&orow[t + 2 * THREADS], o2);
    __stcs(&orow[t + 3 * THREADS], o3);
}

extern "C" void kernel_launch(void* const* d_in, const int* in_sizes, int n_in,
                              void* d_out, int out_size)
{
    const float4* x = (const float4*)d_in[0];
    const float4* scale = (const float4*)d_in[1];
    float4* out = (float4*)d_out;

    const int rows = out_size / D;   // 4 * 4096 = 16384
    mrmsnorm_kernel<<<rows, THREADS>>>(x, scale, out);
}